// round 7
// baseline (speedup 1.0000x reference)
#include <cuda_runtime.h>

#define NBINS   32768
#define N_LEV   1024
#define NSIDE   2048
#define XMIN_F  (-4.25f)
#define XMAX_F  (4.25f)

__device__ float    g_grid[N_LEV];
__device__ float    g_lut[N_LEV];
__device__ unsigned g_out[NBINS];
__device__ uint4    g_side[NSIDE];
__device__ int      g_side_cnt;

// ---------------------------------------------------------------------------
// Exact reference nearest-index (searchsorted 'left' + abs-distance compare).
// ---------------------------------------------------------------------------
__device__ __forceinline__ int nidx_exact_s(float x, const float* __restrict__ grid)
{
    int l = 0, r = N_LEV;                 // first i with grid[i] >= x
    while (l < r) {
        int m = (l + r) >> 1;
        if (grid[m] < x) l = m + 1; else r = m;
    }
    int idx = l < 1 ? 1 : (l > N_LEV - 1 ? N_LEV - 1 : l);
    float left  = grid[idx - 1];
    float right = grid[idx];
    return (fabsf(x - left) < fabsf(x - right)) ? idx - 1 : idx;
}

// Exact largest float x for which reference picks level a over a+1.
// pred(x) = |x-l| < |x-r| is monotone true->false in x (l < r), so fp
// bisection down to adjacent floats gives the bit-exact threshold.
__device__ __forceinline__ float thr_exact(float l, float r)
{
    if (!(l < r)) return __uint_as_float(0xFF800000u);  // -inf (defensive)
    float a = l, bb = r;
    for (int it = 0; it < 64; ++it) {
        float m = 0.5f * (a + bb);
        if (!(m > a && m < bb)) break;                  // adjacent -> done
        if (fabsf(m - l) < fabsf(m - r)) a = m; else bb = m;
    }
    return a;
}

// ---------------------------------------------------------------------------
// Prep 1 (1 block, 1024 threads): grid = h[:,0], lut[i] = chain output,
// reset side counter.
// ---------------------------------------------------------------------------
__global__ void prep_lut(const float* __restrict__ h,
                         const float* __restrict__ d,
                         const float* __restrict__ T,
                         const float* __restrict__ b)
{
    int i = threadIdx.x;
    if (i == 0) g_side_cnt = 0;
    float hv[9];
#pragma unroll
    for (int t = 0; t < 9; ++t) hv[t] = h[i * 9 + t];   // independent loads
    float v = hv[0];
    g_grid[i] = v;
    float out = 0.0f;
#pragma unroll
    for (int t = 1; t <= 8; ++t) {
        if (v - T[t] >= 0.0f) out += d[t];
        if (t != 8) v = hv[t + 1];
    }
    g_lut[i] = out - b[0];
}

// ---------------------------------------------------------------------------
// Prep 2 (64 blocks x 512): one bin per thread.
// Widened edges (+-0.25*W) absorb quantizer fp slop between prep & main.
//  lo == hi           : g_out[j] = final f32 output (hot, ~94% of mass)
//  hi - lo in {1,2}   : side record {X1, X2, idx0|idx1|idx2, 0}
//  hi - lo >= 3 (rare): side record flag=1 -> exact search fallback
// ---------------------------------------------------------------------------
__global__ void prep_bins()
{
    __shared__ float s_grid[N_LEV];
    __shared__ float s_lut[N_LEV];
    for (int i = threadIdx.x; i < N_LEV; i += blockDim.x) {
        s_grid[i] = g_grid[i];
        s_lut[i]  = g_lut[i];
    }
    __syncthreads();

    int j = blockIdx.x * blockDim.x + threadIdx.x;
    if (j >= NBINS) return;

    const float W = (XMAX_F - XMIN_F) / (float)NBINS;
    float eL = XMIN_F + (float)j       * W - 0.25f * W;
    float eR = XMIN_F + (float)(j + 1) * W + 0.25f * W;
    int lo = nidx_exact_s(eL, s_grid);
    int hi = nidx_exact_s(eR, s_grid);

    if (lo == hi) {
        g_out[j] = __float_as_uint(s_lut[lo]);
        return;
    }
    int si = atomicAdd(&g_side_cnt, 1);
    if (si >= NSIDE) si = NSIDE - 1;      // unreachable (<= 2*1023 entries)
    uint4 rec;
    if (hi - lo <= 2) {
        rec.x = __float_as_uint(thr_exact(s_grid[lo], s_grid[lo + 1]));
        rec.y = (hi - lo == 2)
              ? __float_as_uint(thr_exact(s_grid[lo + 1], s_grid[lo + 2]))
              : 0x7F800000u;              // +inf: middle slot absorbs
        int i1 = lo + 1;
        int i2 = hi;
        rec.z = (unsigned)lo | ((unsigned)i1 << 10) | ((unsigned)i2 << 20);
        rec.w = 0u;
    } else {
        rec.x = rec.y = rec.z = 0u;
        rec.w = 1u;                       // exact-search fallback
    }
    g_side[si] = rec;
    g_out[j] = 0xFFC00000u | (unsigned)si;
}

// ---------------------------------------------------------------------------
// Main kernel: hot path = 1 random LDS.32 per element.
// ---------------------------------------------------------------------------
__device__ __forceinline__ float eval_one(float x,
                                          const unsigned* __restrict__ s_out,
                                          const uint4* __restrict__ s_side,
                                          const float* __restrict__ s_grid,
                                          const float* __restrict__ s_lut)
{
    const float scale = (float)NBINS / (XMAX_F - XMIN_F);
    int j = (int)((x - XMIN_F) * scale);
    j = j < 0 ? 0 : (j > NBINS - 1 ? NBINS - 1 : j);
    unsigned u = s_out[j];
    float res = __uint_as_float(u);
    if (u >= 0xFFC00000u) {                       // ~6% of elements
        uint4 rec = s_side[u & (NSIDE - 1u)];
        if (rec.w) {                              // ~0.1%: exact fallback
            res = s_lut[nidx_exact_s(x, s_grid)];
        } else {
            unsigned p = rec.z;
            int idx = (x <= __uint_as_float(rec.x)) ? (int)(p & 1023u)
                    : (x <= __uint_as_float(rec.y)) ? (int)((p >> 10) & 1023u)
                    :                                 (int)((p >> 20) & 1023u);
            res = s_lut[idx];
        }
    }
    return res;
}

#define SMEM_BYTES (NBINS * 4 + NSIDE * 16 + 2 * N_LEV * 4)

__global__ void __launch_bounds__(1024, 1)
ps_act_main(const float4* __restrict__ xin, float4* __restrict__ oout,
            int n4, const float* __restrict__ xs, float* __restrict__ os, int n)
{
    extern __shared__ unsigned char smem_raw[];
    unsigned* const s_out  = (unsigned*)smem_raw;
    uint4*    const s_side = (uint4*)(s_out + NBINS);
    float*    const s_grid = (float*)(s_side + NSIDE);
    float*    const s_lut  = s_grid + N_LEV;

    // coalesced table load (uint4 chunks of g_out)
    {
        const uint4* go4 = (const uint4*)g_out;
        uint4* so4 = (uint4*)s_out;
        for (int i = threadIdx.x; i < NBINS / 4; i += blockDim.x)
            so4[i] = go4[i];
        for (int i = threadIdx.x; i < NSIDE; i += blockDim.x)
            s_side[i] = g_side[i];
        for (int i = threadIdx.x; i < N_LEV; i += blockDim.x) {
            s_grid[i] = g_grid[i];
            s_lut[i]  = g_lut[i];
        }
    }
    __syncthreads();

    const int tid = blockIdx.x * blockDim.x + threadIdx.x;
    const int nt  = gridDim.x * blockDim.x;

    // Coalesced unroll-2 at offsets (i, i+nt): every LDG.128/STG.128 is a
    // fully-coalesced 512B warp transaction; two loads in flight per thread.
    int i = tid;
    for (; i + nt < n4; i += 2 * nt) {
        float4 a = xin[i];
        float4 c = xin[i + nt];
        float4 ra, rc;
        ra.x = eval_one(a.x, s_out, s_side, s_grid, s_lut);
        ra.y = eval_one(a.y, s_out, s_side, s_grid, s_lut);
        ra.z = eval_one(a.z, s_out, s_side, s_grid, s_lut);
        ra.w = eval_one(a.w, s_out, s_side, s_grid, s_lut);
        rc.x = eval_one(c.x, s_out, s_side, s_grid, s_lut);
        rc.y = eval_one(c.y, s_out, s_side, s_grid, s_lut);
        rc.z = eval_one(c.z, s_out, s_side, s_grid, s_lut);
        rc.w = eval_one(c.w, s_out, s_side, s_grid, s_lut);
        oout[i]      = ra;
        oout[i + nt] = rc;
    }
    if (i < n4) {
        float4 a = xin[i];
        float4 ra;
        ra.x = eval_one(a.x, s_out, s_side, s_grid, s_lut);
        ra.y = eval_one(a.y, s_out, s_side, s_grid, s_lut);
        ra.z = eval_one(a.z, s_out, s_side, s_grid, s_lut);
        ra.w = eval_one(a.w, s_out, s_side, s_grid, s_lut);
        oout[i] = ra;
    }

    // scalar tail (empty for this shape)
    for (int k = n4 * 4 + tid; k < n; k += nt)
        os[k] = eval_one(xs[k], s_out, s_side, s_grid, s_lut);
}

// ---------------------------------------------------------------------------
extern "C" void kernel_launch(void* const* d_in, const int* in_sizes, int n_in,
                              void* d_out, int out_size)
{
    const float* x = (const float*)d_in[0];
    const float* h = (const float*)d_in[1];
    const float* d = (const float*)d_in[2];
    const float* T = (const float*)d_in[3];
    const float* b = (const float*)d_in[4];
    float* out = (float*)d_out;
    int n  = in_sizes[0];
    int n4 = n >> 2;

    cudaFuncSetAttribute(ps_act_main,
                         cudaFuncAttributeMaxDynamicSharedMemorySize, SMEM_BYTES);

    prep_lut<<<1, 1024>>>(h, d, T, b);
    prep_bins<<<NBINS / 512, 512>>>();

    ps_act_main<<<152, 1024, SMEM_BYTES>>>((const float4*)x, (float4*)out,
                                           n4, x, out, n);
}

// round 9
// speedup vs baseline: 1.0712x; 1.0712x over previous
#include <cuda_runtime.h>
#include <cuda_fp16.h>

#define NBINS   16384
#define N_LEV   1024
#define XMIN_F  (-4.25f)
#define XMAX_F  (4.25f)

// ---------------------------------------------------------------------------
// Exact reference nearest-index (searchsorted 'left' + abs-distance compare).
// ---------------------------------------------------------------------------
__device__ __forceinline__ int nidx_exact_s(float x, const float* __restrict__ grid)
{
    int l = 0, r = N_LEV;                 // first i with grid[i] >= x
    while (l < r) {
        int m = (l + r) >> 1;
        if (grid[m] < x) l = m + 1; else r = m;
    }
    int idx = l < 1 ? 1 : (l > N_LEV - 1 ? N_LEV - 1 : l);
    float left  = grid[idx - 1];
    float right = grid[idx];
    return (fabsf(x - left) < fabsf(x - right)) ? idx - 1 : idx;
}

// Exact largest float x for which the reference picks the left level of the
// pair (l, r). pred(x) = |x-l| < |x-r| is monotone true->false in x, so fp
// bisection down to adjacent floats yields the bit-exact threshold.
__device__ __forceinline__ float thr_exact(float l, float r)
{
    if (!(l < r)) return __uint_as_float(0xFF800000u);  // -inf: always right
    float a = l, c = r;
    for (int it = 0; it < 64; ++it) {
        float m = 0.5f * (a + c);
        if (!(m > a && m < c)) break;                   // adjacent -> done
        if (fabsf(m - l) < fabsf(m - r)) a = m; else c = m;
    }
    return a;
}

// Pack two f32 outputs as a half2 bit pattern (aliasing-safe).
__device__ __forceinline__ unsigned pack_h2(float lo, float hi)
{
    __half2_raw hr = __halves2half2(__float2half(lo), __float2half(hi));
    return (unsigned)hr.x | ((unsigned)hr.y << 16);
}

// ---------------------------------------------------------------------------
// Branchless hot path: one random LDS.64 per element.
// rec = {thr_bits, half2(outL, outR)}.
//   thr = +inf  : pure bin, both halves identical.
//   finite thr  : exactly one decision boundary; (x <= thr) ? outL : outR.
//   0xFFFFFFFF  : >=2 boundaries in bin (a handful) -> exact f32 fallback.
// ---------------------------------------------------------------------------
__device__ __forceinline__ float eval_one(float x,
                                          const uint2* __restrict__ s_bins,
                                          const float* __restrict__ s_grid,
                                          const float* __restrict__ s_lut)
{
    const float scale = (float)NBINS / (XMAX_F - XMIN_F);
    int j = (int)((x - XMIN_F) * scale);
    j = j < 0 ? 0 : (j > NBINS - 1 ? NBINS - 1 : j);
    uint2 rec = s_bins[j];
    if (rec.x != 0xFFFFFFFFu) {
        __half2_raw hr;
        hr.x = (unsigned short)(rec.y & 0xFFFFu);
        hr.y = (unsigned short)(rec.y >> 16);
        float2 f = __half22float2(__half2(hr));
        return (x <= __uint_as_float(rec.x)) ? f.x : f.y;
    }
    return s_lut[nidx_exact_s(x, s_grid)];      // rare exact fallback
}

#define SMEM_BYTES (NBINS * 8 + 2 * N_LEV * 4)

// ---------------------------------------------------------------------------
// Single fused kernel. Prologue (per CTA, parallel across SMs):
//   1) grid = h[:,0]; lut[i] = chain output (exact reference semantics)
//   2) bin table: strided bins per thread (spreads threshold clusters)
// Main loop: coalesced float4 streaming, branchless table lookups.
// ---------------------------------------------------------------------------
__global__ void __launch_bounds__(1024, 1)
ps_act(const float* __restrict__ h,  const float* __restrict__ d,
       const float* __restrict__ T,  const float* __restrict__ bscal,
       const float4* __restrict__ xin, float4* __restrict__ oout,
       int n4, const float* __restrict__ xs, float* __restrict__ os, int n)
{
    extern __shared__ unsigned char smem_raw[];
    uint2* const s_bins = (uint2*)smem_raw;
    float* const s_grid = (float*)(s_bins + NBINS);
    float* const s_lut  = s_grid + N_LEV;

    const int t0 = threadIdx.x;               // 1024 threads == N_LEV

    // ---- Prologue 1: grid + lut -------------------------------------------
    {
        float hv[9];
#pragma unroll
        for (int t = 0; t < 9; ++t) hv[t] = h[t0 * 9 + t];  // independent loads
        float v = hv[0];
        s_grid[t0] = v;
        float out = 0.0f;
#pragma unroll
        for (int t = 1; t <= 8; ++t) {
            if (v - T[t] >= 0.0f) out += d[t];
            if (t != 8) v = hv[t + 1];
        }
        s_lut[t0] = out - bscal[0];
    }
    __syncthreads();

    // ---- Prologue 2: bin table --------------------------------------------
    // Widened edges (+-0.25*W >> quantizer fp slop) guarantee that every x
    // mapping to bin j has nidx(x) within [nidx(eL), nidx(eR)] (nidx is
    // monotone in x). Outside [XMIN,XMAX] nidx saturates, so the clamped
    // first/last bins are pure and cover the tails exactly.
    {
        const float W = (XMAX_F - XMIN_F) / (float)NBINS;
        for (int j = t0; j < NBINS; j += 1024) {
            float eL = XMIN_F + (float)j       * W - 0.25f * W;
            float eR = XMIN_F + (float)(j + 1) * W + 0.25f * W;
            int lo = nidx_exact_s(eL, s_grid);
            int hi = nidx_exact_s(eR, s_grid);
            uint2 rec;
            if (hi == lo) {
                rec.x = 0x7F800000u;                  // +inf: always left
                rec.y = pack_h2(s_lut[lo], s_lut[lo]);
            } else if (hi == lo + 1) {
                rec.x = __float_as_uint(thr_exact(s_grid[lo], s_grid[hi]));
                rec.y = pack_h2(s_lut[lo], s_lut[hi]);
            } else {
                rec.x = 0xFFFFFFFFu;                  // exact-search fallback
                rec.y = 0u;
            }
            s_bins[j] = rec;
        }
    }
    __syncthreads();

    // ---- Main loop --------------------------------------------------------
    const int tid = blockIdx.x * blockDim.x + t0;
    const int nt  = gridDim.x * blockDim.x;

    // Coalesced unroll-2 at offsets (i, i+nt): every LDG.128/STG.128 is a
    // fully-coalesced 512B warp transaction; two loads in flight per thread.
    int i = tid;
    for (; i + nt < n4; i += 2 * nt) {
        float4 a = xin[i];
        float4 c = xin[i + nt];
        float4 ra, rc;
        ra.x = eval_one(a.x, s_bins, s_grid, s_lut);
        ra.y = eval_one(a.y, s_bins, s_grid, s_lut);
        ra.z = eval_one(a.z, s_bins, s_grid, s_lut);
        ra.w = eval_one(a.w, s_bins, s_grid, s_lut);
        rc.x = eval_one(c.x, s_bins, s_grid, s_lut);
        rc.y = eval_one(c.y, s_bins, s_grid, s_lut);
        rc.z = eval_one(c.z, s_bins, s_grid, s_lut);
        rc.w = eval_one(c.w, s_bins, s_grid, s_lut);
        oout[i]      = ra;
        oout[i + nt] = rc;
    }
    if (i < n4) {
        float4 a = xin[i];
        float4 ra;
        ra.x = eval_one(a.x, s_bins, s_grid, s_lut);
        ra.y = eval_one(a.y, s_bins, s_grid, s_lut);
        ra.z = eval_one(a.z, s_bins, s_grid, s_lut);
        ra.w = eval_one(a.w, s_bins, s_grid, s_lut);
        oout[i] = ra;
    }

    // scalar tail (empty for this shape)
    for (int k = n4 * 4 + tid; k < n; k += nt)
        os[k] = eval_one(xs[k], s_bins, s_grid, s_lut);
}

// ---------------------------------------------------------------------------
extern "C" void kernel_launch(void* const* d_in, const int* in_sizes, int n_in,
                              void* d_out, int out_size)
{
    const float* x = (const float*)d_in[0];
    const float* h = (const float*)d_in[1];
    const float* d = (const float*)d_in[2];
    const float* T = (const float*)d_in[3];
    const float* b = (const float*)d_in[4];
    float* out = (float*)d_out;
    int n  = in_sizes[0];
    int n4 = n >> 2;

    cudaFuncSetAttribute(ps_act,
                         cudaFuncAttributeMaxDynamicSharedMemorySize, SMEM_BYTES);

    ps_act<<<152, 1024, SMEM_BYTES>>>(h, d, T, b,
                                      (const float4*)x, (float4*)out,
                                      n4, x, out, n);
}

// round 11
// speedup vs baseline: 1.1959x; 1.1163x over previous
#include <cuda_runtime.h>
#include <cuda_fp16.h>

#define NBINS   16384
#define N_LEV   1024
#define XMIN_F  (-4.25f)
#define XMAX_F  (4.25f)

// ---------------------------------------------------------------------------
// Exact reference nearest-index (searchsorted 'left' + abs-distance compare).
// ---------------------------------------------------------------------------
__device__ __forceinline__ int nidx_exact_s(float x, const float* __restrict__ grid)
{
    int l = 0, r = N_LEV;                 // first i with grid[i] >= x
    while (l < r) {
        int m = (l + r) >> 1;
        if (grid[m] < x) l = m + 1; else r = m;
    }
    int idx = l < 1 ? 1 : (l > N_LEV - 1 ? N_LEV - 1 : l);
    float left  = grid[idx - 1];
    float right = grid[idx];
    return (fabsf(x - left) < fabsf(x - right)) ? idx - 1 : idx;
}

// Monotone walk form of nidx: advance while the nearest-compare predicate
// says "not yet". Proven identical to nidx_exact_s for all x (ties -> right,
// end clamps included), given sorted distinct levels.
__device__ __forceinline__ int nidx_walk(float x, int idx,
                                         const float* __restrict__ grid)
{
    while (idx < N_LEV - 1 &&
           !(fabsf(x - grid[idx]) < fabsf(x - grid[idx + 1])))
        ++idx;
    return idx;
}

// Exact largest float x for which the reference picks the left level of the
// pair (l, r). pred(x) = |x-l| < |x-r| is monotone true->false in x, so fp
// bisection down to adjacent floats yields the bit-exact threshold.
__device__ __forceinline__ float thr_exact(float l, float r)
{
    if (!(l < r)) return __uint_as_float(0xFF800000u);  // -inf: always right
    float a = l, c = r;
    for (int it = 0; it < 64; ++it) {
        float m = 0.5f * (a + c);
        if (!(m > a && m < c)) break;                   // adjacent -> done
        if (fabsf(m - l) < fabsf(m - r)) a = m; else c = m;
    }
    return a;
}

// Pack two f32 outputs as a half2 bit pattern (prologue only).
__device__ __forceinline__ unsigned pack_h2(float lo, float hi)
{
    __half2_raw hr = __halves2half2(__float2half(lo), __float2half(hi));
    return (unsigned)hr.x | ((unsigned)hr.y << 16);
}

// ---------------------------------------------------------------------------
// Branchless hot path: one random LDS.64 per element.
// rec = {thr_bits, half2(outL, outR)}.
//   thr = +inf  : pure bin (both halves equal)
//   finite thr  : one boundary; (x <= thr) ? outL : outR   (thr is exact)
//   0xFFFFFFFF  : >=2 boundaries (a handful of bins) -> exact f32 fallback
// Decode uses H0/H1 F2F selectors only — no shifts, no repacking.
// ---------------------------------------------------------------------------
__device__ __forceinline__ float eval_one(float x,
                                          const uint2* __restrict__ s_bins,
                                          const float* __restrict__ s_grid,
                                          const float* __restrict__ s_lut)
{
    const float scale = (float)NBINS / (XMAX_F - XMIN_F);
    float xc = fmaxf(x, XMIN_F);
    int j = (int)((xc - XMIN_F) * scale);
    j = j > NBINS - 1 ? NBINS - 1 : j;
    uint2 rec = s_bins[j];
    __half2 h2 = *reinterpret_cast<const __half2*>(&rec.y);
    float fl = __low2float(h2);                   // F2F.F32.F16.H0
    float fh = __high2float(h2);                  // F2F.F32.F16.H1
    float res = (x <= __uint_as_float(rec.x)) ? fl : fh;
    if (rec.x == 0xFFFFFFFFu)                     // ~0.03% of elements
        res = s_lut[nidx_exact_s(x, s_grid)];
    return res;
}

#define SMEM_BYTES (NBINS * 8 + 2 * N_LEV * 4)

// ---------------------------------------------------------------------------
// Single fused kernel. Prologue (per CTA, parallel across all SMs):
//   1) grid = h[:,0]; lut[i] = chain output (exact reference semantics)
//   2) bin table: 16 CONTIGUOUS bins/thread; ONE binary search for the first
//      widened edge, then monotone walks for every subsequent edge.
// Main loop: coalesced float4 streaming, branchless 8B-record lookups.
// ---------------------------------------------------------------------------
__global__ void __launch_bounds__(1024, 1)
ps_act(const float* __restrict__ h,  const float* __restrict__ d,
       const float* __restrict__ T,  const float* __restrict__ bscal,
       const float4* __restrict__ xin, float4* __restrict__ oout,
       int n4, const float* __restrict__ xs, float* __restrict__ os, int n)
{
    extern __shared__ unsigned char smem_raw[];
    uint2* const s_bins = (uint2*)smem_raw;
    float* const s_grid = (float*)(s_bins + NBINS);
    float* const s_lut  = s_grid + N_LEV;

    const int t0 = threadIdx.x;               // 1024 threads == N_LEV

    // ---- Prologue 1: grid + lut -------------------------------------------
    {
        float hv[9];
#pragma unroll
        for (int t = 0; t < 9; ++t) hv[t] = h[t0 * 9 + t];  // independent loads
        float v = hv[0];
        s_grid[t0] = v;
        float out = 0.0f;
#pragma unroll
        for (int t = 1; t <= 8; ++t) {
            if (v - T[t] >= 0.0f) out += d[t];
            if (t != 8) v = hv[t + 1];
        }
        s_lut[t0] = out - bscal[0];
    }
    __syncthreads();

    // ---- Prologue 2: bin table (search once, then walk) -------------------
    // Widened edges (+-0.25*W >> fp slop of the main-loop bin quantizer)
    // guarantee nidx(x) in [lo, hi] for every x mapping to bin j; nidx is
    // monotone so lo/hi advance with the edges -> cheap forward walks.
    {
        const float W   = (XMAX_F - XMIN_F) / (float)NBINS;
        const int   BPT = NBINS / 1024;       // 16 contiguous bins per thread
        const int   j0  = t0 * BPT;

        int lo = nidx_exact_s(XMIN_F + (float)j0 * W - 0.25f * W, s_grid);
#pragma unroll 1
        for (int j = j0; j < j0 + BPT; ++j) {
            float eRw = XMIN_F + (float)(j + 1) * W + 0.25f * W;
            int hi = nidx_walk(eRw, lo, s_grid);
            uint2 rec;
            if (hi == lo) {
                rec.x = 0x7F800000u;                  // +inf: always left
                rec.y = pack_h2(s_lut[lo], s_lut[lo]);
            } else if (hi == lo + 1) {
                rec.x = __float_as_uint(thr_exact(s_grid[lo], s_grid[hi]));
                rec.y = pack_h2(s_lut[lo], s_lut[hi]);
            } else {
                rec.x = 0xFFFFFFFFu;                  // exact-search fallback
                rec.y = 0u;
            }
            s_bins[j] = rec;
            float eLn = XMIN_F + (float)(j + 1) * W - 0.25f * W;
            lo = nidx_walk(eLn, lo, s_grid);          // next bin's lo
        }
    }
    __syncthreads();

    // ---- Main loop --------------------------------------------------------
    const int tid = blockIdx.x * blockDim.x + t0;
    const int nt  = gridDim.x * blockDim.x;

    // Coalesced unroll-2 at offsets (i, i+nt): every LDG.128/STG.128 is a
    // fully-coalesced 512B warp transaction; two loads in flight per thread.
    int i = tid;
    for (; i + nt < n4; i += 2 * nt) {
        float4 a = xin[i];
        float4 c = xin[i + nt];
        float4 ra, rc;
        ra.x = eval_one(a.x, s_bins, s_grid, s_lut);
        ra.y = eval_one(a.y, s_bins, s_grid, s_lut);
        ra.z = eval_one(a.z, s_bins, s_grid, s_lut);
        ra.w = eval_one(a.w, s_bins, s_grid, s_lut);
        rc.x = eval_one(c.x, s_bins, s_grid, s_lut);
        rc.y = eval_one(c.y, s_bins, s_grid, s_lut);
        rc.z = eval_one(c.z, s_bins, s_grid, s_lut);
        rc.w = eval_one(c.w, s_bins, s_grid, s_lut);
        oout[i]      = ra;
        oout[i + nt] = rc;
    }
    if (i < n4) {
        float4 a = xin[i];
        float4 ra;
        ra.x = eval_one(a.x, s_bins, s_grid, s_lut);
        ra.y = eval_one(a.y, s_bins, s_grid, s_lut);
        ra.z = eval_one(a.z, s_bins, s_grid, s_lut);
        ra.w = eval_one(a.w, s_bins, s_grid, s_lut);
        oout[i] = ra;
    }

    // scalar tail (empty for this shape)
    for (int k = n4 * 4 + tid; k < n; k += nt)
        os[k] = eval_one(xs[k], s_bins, s_grid, s_lut);
}

// ---------------------------------------------------------------------------
extern "C" void kernel_launch(void* const* d_in, const int* in_sizes, int n_in,
                              void* d_out, int out_size)
{
    const float* x = (const float*)d_in[0];
    const float* h = (const float*)d_in[1];
    const float* d = (const float*)d_in[2];
    const float* T = (const float*)d_in[3];
    const float* b = (const float*)d_in[4];
    float* out = (float*)d_out;
    int n  = in_sizes[0];
    int n4 = n >> 2;

    cudaFuncSetAttribute(ps_act,
                         cudaFuncAttributeMaxDynamicSharedMemorySize, SMEM_BYTES);

    ps_act<<<152, 1024, SMEM_BYTES>>>(h, d, T, b,
                                      (const float4*)x, (float4*)out,
                                      n4, x, out, n);
}

// round 12
// speedup vs baseline: 1.2879x; 1.0770x over previous
#include <cuda_runtime.h>
#include <cuda_fp16.h>

#define NBINS   8192
#define N_LEV   1024
#define XMIN_F  (-4.25f)
#define XMAX_F  (4.25f)

// ---------------------------------------------------------------------------
// Exact reference nearest-index (searchsorted 'left' + abs-distance compare).
// ---------------------------------------------------------------------------
__device__ __forceinline__ int nidx_exact_s(float x, const float* __restrict__ grid)
{
    int l = 0, r = N_LEV;                 // first i with grid[i] >= x
    while (l < r) {
        int m = (l + r) >> 1;
        if (grid[m] < x) l = m + 1; else r = m;
    }
    int idx = l < 1 ? 1 : (l > N_LEV - 1 ? N_LEV - 1 : l);
    float left  = grid[idx - 1];
    float right = grid[idx];
    return (fabsf(x - left) < fabsf(x - right)) ? idx - 1 : idx;
}

// Monotone walk form of nidx: advance while the nearest-compare predicate
// says "not yet". Identical to nidx_exact_s for all x (ties -> right,
// end clamps included), given sorted distinct levels.
__device__ __forceinline__ int nidx_walk(float x, int idx,
                                         const float* __restrict__ grid)
{
    while (idx < N_LEV - 1 &&
           !(fabsf(x - grid[idx]) < fabsf(x - grid[idx + 1])))
        ++idx;
    return idx;
}

// Exact largest float x for which the reference picks the left level of the
// pair (l, r). pred(x) = |x-l| < |x-r| is monotone true->false in x, so fp
// bisection down to adjacent floats yields the bit-exact threshold.
__device__ __forceinline__ float thr_exact(float l, float r)
{
    if (!(l < r)) return __uint_as_float(0xFF800000u);  // -inf: always right
    float a = l, c = r;
    for (int it = 0; it < 64; ++it) {
        float m = 0.5f * (a + c);
        if (!(m > a && m < c)) break;                   // adjacent -> done
        if (fabsf(m - l) < fabsf(m - r)) a = m; else c = m;
    }
    return a;
}

// Pack two f32 outputs as a half2 bit pattern (prologue only).
__device__ __forceinline__ unsigned pack_h2(float lo, float hi)
{
    __half2_raw hr = __halves2half2(__float2half(lo), __float2half(hi));
    return (unsigned)hr.x | ((unsigned)hr.y << 16);
}

// ---------------------------------------------------------------------------
// Branchless hot path: one random LDS.64 per element.
// rec = {thr_bits, half2(outL, outR)}.
//   thr = +inf  : pure bin (both halves equal)
//   finite thr  : one boundary; (x <= thr) ? outL : outR   (thr is exact)
//   0xFFFFFFFF  : >=2 boundaries (rare) -> exact f32 fallback
// Decode: PRMT selects the chosen f16, then ONE cvt. No shifts, no repack.
// ---------------------------------------------------------------------------
__device__ __forceinline__ float eval_one(float x,
                                          const uint2* __restrict__ s_bins,
                                          const float* __restrict__ s_grid,
                                          const float* __restrict__ s_lut)
{
    const float scale = (float)NBINS / (XMAX_F - XMIN_F);
    const float offs  = -XMIN_F * scale;
    float xc = fmaxf(x, XMIN_F);
    int j = (int)fmaf(xc, scale, offs);            // FFMA + F2I
    j = j > NBINS - 1 ? NBINS - 1 : j;             // IMNMX
    uint2 rec = s_bins[j];                         // LDS.64
    bool left = (x <= __uint_as_float(rec.x));     // FSETP
    unsigned sel   = left ? 0x5410u : 0x5432u;     // SEL
    unsigned hbits = __byte_perm(rec.y, 0u, sel);  // PRMT -> chosen f16
    __half_raw hr; hr.x = (unsigned short)hbits;
    float res = __half2float(__half(hr));          // single F2F
    if (rec.x == 0xFFFFFFFFu)                      // ~0.1% of elements
        res = s_lut[nidx_exact_s(x, s_grid)];
    return res;
}

#define SMEM_BYTES (NBINS * 8 + 2 * N_LEV * 4)

// ---------------------------------------------------------------------------
// Single fused kernel, 2 CTAs/SM (64 warps). Prologue per CTA:
//   1) grid = h[:,0]; lut[i] = chain output (exact reference semantics)
//   2) bin table: 8 contiguous bins/thread; ONE binary search for the first
//      widened edge, then monotone walks for every subsequent edge.
// Main loop: coalesced float4 streaming, branchless 8B-record lookups.
// ---------------------------------------------------------------------------
__global__ void __launch_bounds__(1024, 2)
ps_act(const float* __restrict__ h,  const float* __restrict__ d,
       const float* __restrict__ T,  const float* __restrict__ bscal,
       const float4* __restrict__ xin, float4* __restrict__ oout,
       int n4, const float* __restrict__ xs, float* __restrict__ os, int n)
{
    extern __shared__ unsigned char smem_raw[];
    uint2* const s_bins = (uint2*)smem_raw;
    float* const s_grid = (float*)(s_bins + NBINS);
    float* const s_lut  = s_grid + N_LEV;

    const int t0 = threadIdx.x;               // 1024 threads == N_LEV

    // ---- Prologue 1: grid + lut -------------------------------------------
    {
        float hv[9];
#pragma unroll
        for (int t = 0; t < 9; ++t) hv[t] = h[t0 * 9 + t];  // independent loads
        float v = hv[0];
        s_grid[t0] = v;
        float out = 0.0f;
#pragma unroll
        for (int t = 1; t <= 8; ++t) {
            if (v - T[t] >= 0.0f) out += d[t];
            if (t != 8) v = hv[t + 1];
        }
        s_lut[t0] = out - bscal[0];
    }
    __syncthreads();

    // ---- Prologue 2: bin table (search once, then walk) -------------------
    // Widened edges (+-0.25*W >> fp slop of the main-loop fmaf quantizer)
    // guarantee nidx(x) in [lo, hi] for every x mapping to bin j; nidx is
    // monotone so lo/hi advance with the edges -> cheap forward walks.
    {
        const float W   = (XMAX_F - XMIN_F) / (float)NBINS;
        const int   BPT = NBINS / 1024;       // 8 contiguous bins per thread
        const int   j0  = t0 * BPT;

        int lo = nidx_exact_s(XMIN_F + (float)j0 * W - 0.25f * W, s_grid);
#pragma unroll 1
        for (int j = j0; j < j0 + BPT; ++j) {
            float eRw = XMIN_F + (float)(j + 1) * W + 0.25f * W;
            int hi = nidx_walk(eRw, lo, s_grid);
            uint2 rec;
            if (hi == lo) {
                rec.x = 0x7F800000u;                  // +inf: always left
                rec.y = pack_h2(s_lut[lo], s_lut[lo]);
            } else if (hi == lo + 1) {
                rec.x = __float_as_uint(thr_exact(s_grid[lo], s_grid[hi]));
                rec.y = pack_h2(s_lut[lo], s_lut[hi]);
            } else {
                rec.x = 0xFFFFFFFFu;                  // exact-search fallback
                rec.y = 0u;
            }
            s_bins[j] = rec;
            float eLn = XMIN_F + (float)(j + 1) * W - 0.25f * W;
            lo = nidx_walk(eLn, lo, s_grid);          // next bin's lo
        }
    }
    __syncthreads();

    // ---- Main loop --------------------------------------------------------
    const int tid = blockIdx.x * blockDim.x + t0;
    const int nt  = gridDim.x * blockDim.x;

    // Coalesced unroll-2 at offsets (i, i+nt): every LDG.128/STG.128 is a
    // fully-coalesced 512B warp transaction; two loads in flight per thread.
    int i = tid;
    for (; i + nt < n4; i += 2 * nt) {
        float4 a = xin[i];
        float4 c = xin[i + nt];
        float4 ra, rc;
        ra.x = eval_one(a.x, s_bins, s_grid, s_lut);
        ra.y = eval_one(a.y, s_bins, s_grid, s_lut);
        ra.z = eval_one(a.z, s_bins, s_grid, s_lut);
        ra.w = eval_one(a.w, s_bins, s_grid, s_lut);
        rc.x = eval_one(c.x, s_bins, s_grid, s_lut);
        rc.y = eval_one(c.y, s_bins, s_grid, s_lut);
        rc.z = eval_one(c.z, s_bins, s_grid, s_lut);
        rc.w = eval_one(c.w, s_bins, s_grid, s_lut);
        oout[i]      = ra;
        oout[i + nt] = rc;
    }
    if (i < n4) {
        float4 a = xin[i];
        float4 ra;
        ra.x = eval_one(a.x, s_bins, s_grid, s_lut);
        ra.y = eval_one(a.y, s_bins, s_grid, s_lut);
        ra.z = eval_one(a.z, s_bins, s_grid, s_lut);
        ra.w = eval_one(a.w, s_bins, s_grid, s_lut);
        oout[i] = ra;
    }

    // scalar tail (empty for this shape)
    for (int k = n4 * 4 + tid; k < n; k += nt)
        os[k] = eval_one(xs[k], s_bins, s_grid, s_lut);
}

// ---------------------------------------------------------------------------
extern "C" void kernel_launch(void* const* d_in, const int* in_sizes, int n_in,
                              void* d_out, int out_size)
{
    const float* x = (const float*)d_in[0];
    const float* h = (const float*)d_in[1];
    const float* d = (const float*)d_in[2];
    const float* T = (const float*)d_in[3];
    const float* b = (const float*)d_in[4];
    float* out = (float*)d_out;
    int n  = in_sizes[0];
    int n4 = n >> 2;

    cudaFuncSetAttribute(ps_act,
                         cudaFuncAttributeMaxDynamicSharedMemorySize, SMEM_BYTES);

    ps_act<<<304, 1024, SMEM_BYTES>>>(h, d, T, b,
                                      (const float4*)x, (float4*)out,
                                      n4, x, out, n);
}

// round 13
// speedup vs baseline: 1.3285x; 1.0315x over previous
#include <cuda_runtime.h>

#define NBINS   8192
#define N_LEV   1024
#define XMIN_F  (-4.25f)
#define XMAX_F  (4.25f)

// ---------------------------------------------------------------------------
// Exact reference nearest-index (searchsorted 'left' + abs-distance compare).
// ---------------------------------------------------------------------------
__device__ __forceinline__ int nidx_exact_s(float x, const float* __restrict__ grid)
{
    int l = 0, r = N_LEV;                 // first i with grid[i] >= x
    while (l < r) {
        int m = (l + r) >> 1;
        if (grid[m] < x) l = m + 1; else r = m;
    }
    int idx = l < 1 ? 1 : (l > N_LEV - 1 ? N_LEV - 1 : l);
    float left  = grid[idx - 1];
    float right = grid[idx];
    return (fabsf(x - left) < fabsf(x - right)) ? idx - 1 : idx;
}

// Monotone walk form of nidx: advance while the nearest-compare predicate
// says "not yet". Identical to nidx_exact_s for all x (ties -> right,
// end clamps included), given sorted distinct levels.
__device__ __forceinline__ int nidx_walk(float x, int idx,
                                         const float* __restrict__ grid)
{
    while (idx < N_LEV - 1 &&
           !(fabsf(x - grid[idx]) < fabsf(x - grid[idx + 1])))
        ++idx;
    return idx;
}

// Exact largest float x for which the reference picks the left level of the
// pair (l, r). pred(x) = |x-l| < |x-r| is monotone true->false in x, so fp
// bisection down to adjacent floats yields the bit-exact threshold.
__device__ __forceinline__ float thr_exact(float l, float r)
{
    if (!(l < r)) return __uint_as_float(0xFF800000u);  // -inf: always right
    float a = l, c = r;
    for (int it = 0; it < 64; ++it) {
        float m = 0.5f * (a + c);
        if (!(m > a && m < c)) break;                   // adjacent -> done
        if (fabsf(m - l) < fabsf(m - r)) a = m; else c = m;
    }
    return a;
}

// ---------------------------------------------------------------------------
// Branchless hot path: one LDS.128 per element, f32 outputs (exact).
// rec = {thr_bits, outL_f32, outR_f32, flag}.
//   flag=0, thr=+inf : pure bin (outL == outR)
//   flag=0, thr finite: one boundary; (x <= thr) ? outL : outR (thr exact)
//   flag=1           : >=2 boundaries (~128 bins, ~0.5% mass) -> walk
// ---------------------------------------------------------------------------
__device__ __forceinline__ float eval_one(float x,
                                          const uint4* __restrict__ s_bins,
                                          const float* __restrict__ s_grid,
                                          const float* __restrict__ s_lut)
{
    const float scale = (float)NBINS / (XMAX_F - XMIN_F);
    const float offs  = -XMIN_F * scale;
    float xc = fmaxf(x, XMIN_F);
    int j = (int)fmaf(xc, scale, offs);            // FFMA + F2I
    j = j > NBINS - 1 ? NBINS - 1 : j;             // IMNMX
    uint4 rec = s_bins[j];                         // LDS.128
    float res = (x <= __uint_as_float(rec.x)) ? __uint_as_float(rec.y)
                                              : __uint_as_float(rec.z);
    if (rec.w) {                                   // rare bounded walk
        int lo = (int)(rec.y & 0xFFFFu);
        float gl = s_grid[lo];
        int hi = (int)(rec.y >> 16);
        while (lo < hi) {
            float gr = s_grid[lo + 1];
            if (fabsf(x - gl) < fabsf(x - gr)) break;   // exact tie-break
            ++lo; gl = gr;
        }
        res = s_lut[lo];
    }
    return res;
}

#define SMEM_BYTES (NBINS * 16 + 2 * N_LEV * 4)

// ---------------------------------------------------------------------------
// Single fused kernel, 1 CTA/SM (136KB smem). Prologue per CTA:
//   1) grid = h[:,0]; lut[i] = chain output (exact reference semantics)
//   2) bin table: 8 contiguous bins/thread; ONE binary search for the first
//      widened edge, then monotone walks for every subsequent edge.
// Main loop: coalesced float4 streaming, branchless 16B-record lookups.
// ---------------------------------------------------------------------------
__global__ void __launch_bounds__(1024, 1)
ps_act(const float* __restrict__ h,  const float* __restrict__ d,
       const float* __restrict__ T,  const float* __restrict__ bscal,
       const float4* __restrict__ xin, float4* __restrict__ oout,
       int n4, const float* __restrict__ xs, float* __restrict__ os, int n)
{
    extern __shared__ unsigned char smem_raw[];
    uint4* const s_bins = (uint4*)smem_raw;
    float* const s_grid = (float*)(s_bins + NBINS);
    float* const s_lut  = s_grid + N_LEV;

    const int t0 = threadIdx.x;               // 1024 threads == N_LEV

    // ---- Prologue 1: grid + lut -------------------------------------------
    {
        float hv[9];
#pragma unroll
        for (int t = 0; t < 9; ++t) hv[t] = h[t0 * 9 + t];  // independent loads
        float v = hv[0];
        s_grid[t0] = v;
        float out = 0.0f;
#pragma unroll
        for (int t = 1; t <= 8; ++t) {
            if (v - T[t] >= 0.0f) out += d[t];
            if (t != 8) v = hv[t + 1];
        }
        s_lut[t0] = out - bscal[0];
    }
    __syncthreads();

    // ---- Prologue 2: bin table (search once, then walk) -------------------
    // Widened edges (+-0.25*W >> fp slop of the main-loop fmaf quantizer)
    // guarantee nidx(x) in [lo, hi] for every x mapping to bin j; nidx is
    // monotone so lo/hi advance with the edges -> cheap forward walks.
    {
        const float W   = (XMAX_F - XMIN_F) / (float)NBINS;
        const int   BPT = NBINS / 1024;       // 8 contiguous bins per thread
        const int   j0  = t0 * BPT;

        int lo = nidx_exact_s(XMIN_F + (float)j0 * W - 0.25f * W, s_grid);
#pragma unroll 1
        for (int j = j0; j < j0 + BPT; ++j) {
            float eRw = XMIN_F + (float)(j + 1) * W + 0.25f * W;
            int hi = nidx_walk(eRw, lo, s_grid);
            uint4 rec;
            if (hi == lo) {
                rec.x = 0x7F800000u;                  // +inf: always left
                rec.y = __float_as_uint(s_lut[lo]);
                rec.z = rec.y;
                rec.w = 0u;
            } else if (hi == lo + 1) {
                rec.x = __float_as_uint(thr_exact(s_grid[lo], s_grid[hi]));
                rec.y = __float_as_uint(s_lut[lo]);
                rec.z = __float_as_uint(s_lut[hi]);
                rec.w = 0u;
            } else {
                rec.x = 0u;                           // walk fallback
                rec.y = (unsigned)lo | ((unsigned)hi << 16);
                rec.z = 0u;
                rec.w = 1u;
            }
            s_bins[j] = rec;
            float eLn = XMIN_F + (float)(j + 1) * W - 0.25f * W;
            lo = nidx_walk(eLn, lo, s_grid);          // next bin's lo
        }
    }
    __syncthreads();

    // ---- Main loop --------------------------------------------------------
    const int tid = blockIdx.x * blockDim.x + t0;
    const int nt  = gridDim.x * blockDim.x;

    // Coalesced unroll-2 at offsets (i, i+nt): every LDG.128/STG.128 is a
    // fully-coalesced 512B warp transaction; two loads in flight per thread.
    int i = tid;
    for (; i + nt < n4; i += 2 * nt) {
        float4 a = xin[i];
        float4 c = xin[i + nt];
        float4 ra, rc;
        ra.x = eval_one(a.x, s_bins, s_grid, s_lut);
        ra.y = eval_one(a.y, s_bins, s_grid, s_lut);
        ra.z = eval_one(a.z, s_bins, s_grid, s_lut);
        ra.w = eval_one(a.w, s_bins, s_grid, s_lut);
        rc.x = eval_one(c.x, s_bins, s_grid, s_lut);
        rc.y = eval_one(c.y, s_bins, s_grid, s_lut);
        rc.z = eval_one(c.z, s_bins, s_grid, s_lut);
        rc.w = eval_one(c.w, s_bins, s_grid, s_lut);
        oout[i]      = ra;
        oout[i + nt] = rc;
    }
    if (i < n4) {
        float4 a = xin[i];
        float4 ra;
        ra.x = eval_one(a.x, s_bins, s_grid, s_lut);
        ra.y = eval_one(a.y, s_bins, s_grid, s_lut);
        ra.z = eval_one(a.z, s_bins, s_grid, s_lut);
        ra.w = eval_one(a.w, s_bins, s_grid, s_lut);
        oout[i] = ra;
    }

    // scalar tail (empty for this shape)
    for (int k = n4 * 4 + tid; k < n; k += nt)
        os[k] = eval_one(xs[k], s_bins, s_grid, s_lut);
}

// ---------------------------------------------------------------------------
extern "C" void kernel_launch(void* const* d_in, const int* in_sizes, int n_in,
                              void* d_out, int out_size)
{
    const float* x = (const float*)d_in[0];
    const float* h = (const float*)d_in[1];
    const float* d = (const float*)d_in[2];
    const float* T = (const float*)d_in[3];
    const float* b = (const float*)d_in[4];
    float* out = (float*)d_out;
    int n  = in_sizes[0];
    int n4 = n >> 2;

    cudaFuncSetAttribute(ps_act,
                         cudaFuncAttributeMaxDynamicSharedMemorySize, SMEM_BYTES);

    ps_act<<<152, 1024, SMEM_BYTES>>>(h, d, T, b,
                                      (const float4*)x, (float4*)out,
                                      n4, x, out, n);
}